// round 10
// baseline (speedup 1.0000x reference)
#include <cuda_runtime.h>

#define NF   8192   // features
#define ND   64     // coordinate dim
#define KNB  8      // neighbors
#define RT   64     // rows per CTA
#define CT   128    // cols per chunk

// Scratch: __device__ globals (no allocation allowed anywhere).
__device__ __align__(16) float g_sq[NF];
__device__ __align__(16) int   g_idx[NF * KNB];

// ---------------------------------------------------------------------------
// Kernel 1: per-feature squared norm. coordinates layout: [dim][feature].
// Matches reference's sum(square(x)) with separate mul+add rounding.
// ---------------------------------------------------------------------------
__global__ void sq_kernel(const float* __restrict__ crd) {
    int f = blockIdx.x * 256 + threadIdx.x;
    float s = 0.f;
#pragma unroll
    for (int d = 0; d < ND; ++d) {
        float c = crd[d * NF + f];
        s = __fadd_rn(s, __fmul_rn(c, c));
    }
    g_sq[f] = s;
}

// ---------------------------------------------------------------------------
// Kernel 2: fused distance-GEMM + per-row top-8 (value asc, index asc).
// Key = (float_bits(dist) << 13) | col  -> single u64 lexicographic compare.
// ---------------------------------------------------------------------------
__global__ __launch_bounds__(256) void topk_kernel(const float* __restrict__ crd) {
    __shared__ __align__(16) union {
        struct { float rowT[ND][RT]; float colT[ND][CT]; } t;  // 16KB + 32KB
        unsigned long long cand[32][129];                       // 33KB (padded vs bank conflicts)
    } sm;

    const int tid = threadIdx.x;
    const int tx  = tid & 15;          // 16 col-groups  (8 cols each)
    const int ty  = tid >> 4;          // 16 row-groups  (4 rows each)
    const int rowBase = blockIdx.x * RT;

    // Load row tile, [dim][row] layout (coordinates are already [dim][feature]).
    for (int i = tid; i < ND * RT / 4; i += 256) {
        int d = i >> 4, r4 = i & 15;
        *(float4*)&sm.t.rowT[d][r4 * 4] =
            *(const float4*)&crd[d * NF + rowBase + r4 * 4];
    }

    // Per-thread top-8 state for 4 rows: u64 keys + cached max + sqrt gate.
    unsigned long long lst[4][8];
    unsigned long long cmax[4];
    float gate[4];
    const unsigned long long INFKEY = ((unsigned long long)0x7F800000u) << 13;
#pragma unroll
    for (int i = 0; i < 4; ++i) {
#pragma unroll
        for (int s = 0; s < 8; ++s) lst[i][s] = INFKEY | (unsigned)s;  // distinct sentinels
        cmax[i] = INFKEY | 7u;
        gate[i] = __int_as_float(0x7F800000);  // +inf
    }

    float sqr[4];
#pragma unroll
    for (int i = 0; i < 4; ++i) sqr[i] = g_sq[rowBase + ty * 4 + i];

    for (int cb = 0; cb < NF; cb += CT) {
        __syncthreads();  // previous chunk fully consumed
        for (int i = tid; i < ND * CT / 4; i += 256) {
            int d = i >> 5, c4 = i & 31;
            *(float4*)&sm.t.colT[d][c4 * 4] =
                *(const float4*)&crd[d * NF + cb + c4 * 4];
        }
        __syncthreads();

        float sqc[8];
        {
            float4 s0 = *(const float4*)&g_sq[cb + tx * 8];
            float4 s1 = *(const float4*)&g_sq[cb + tx * 8 + 4];
            sqc[0]=s0.x; sqc[1]=s0.y; sqc[2]=s0.z; sqc[3]=s0.w;
            sqc[4]=s1.x; sqc[5]=s1.y; sqc[6]=s1.z; sqc[7]=s1.w;
        }

        float acc[4][8];
#pragma unroll
        for (int i = 0; i < 4; ++i)
#pragma unroll
            for (int j = 0; j < 8; ++j) acc[i][j] = 0.f;

        // Main GEMM micro-kernel: 3 x LDS.128 + 32 FFMA per k-step.
#pragma unroll 8
        for (int kk = 0; kk < ND; ++kk) {
            float4 a  = *(const float4*)&sm.t.rowT[kk][ty * 4];
            float4 b0 = *(const float4*)&sm.t.colT[kk][tx * 8];
            float4 b1 = *(const float4*)&sm.t.colT[kk][tx * 8 + 4];
            float av[4] = {a.x, a.y, a.z, a.w};
            float bv[8] = {b0.x, b0.y, b0.z, b0.w, b1.x, b1.y, b1.z, b1.w};
#pragma unroll
            for (int i = 0; i < 4; ++i)
#pragma unroll
                for (int j = 0; j < 8; ++j)
                    acc[i][j] = fmaf(av[i], bv[j], acc[i][j]);
        }

        // Selection update. Replicate reference elementwise ops exactly:
        // d = (-2*dot + sq_col) + sq_row; dist = sqrt(max(d,0)).
#pragma unroll
        for (int j = 0; j < 8; ++j) {
            int col = cb + tx * 8 + j;
#pragma unroll
            for (int i = 0; i < 4; ++i) {
                float t0  = __fadd_rn(__fmul_rn(-2.f, acc[i][j]), sqc[j]);
                float dsq = __fadd_rn(t0, sqr[i]);
                if (dsq < gate[i]) {   // cheap gate: skip sqrt for ~96% of candidates
                    float dist = __fsqrt_rn(fmaxf(dsq, 0.f));
                    unsigned long long key =
                        (((unsigned long long)__float_as_uint(dist)) << 13) |
                        (unsigned)col;
                    if (key < cmax[i]) {
#pragma unroll
                        for (int s = 0; s < 8; ++s)   // keys unique -> exactly one match
                            if (lst[i][s] == cmax[i]) lst[i][s] = key;
                        unsigned long long m = lst[i][0];
#pragma unroll
                        for (int s = 1; s < 8; ++s) m = (lst[i][s] > m) ? lst[i][s] : m;
                        cmax[i] = m;
                        float dm = __uint_as_float((unsigned)(cmax[i] >> 13));
                        // gate margin guarantees no legit (dist-tie, lower-idx) candidate is skipped
                        gate[i] = __fmul_rn(__fmul_rn(dm, dm), 1.00001f);
                    }
                }
            }
        }
    }

    // Merge 16 column-group lists per row -> final sorted top-8. Two halves
    // of 32 rows so the candidate buffer fits in the smem union.
    __syncthreads();
    for (int half = 0; half < 2; ++half) {
        if ((ty >> 3) == half) {
            int tyl = ty & 7;
#pragma unroll
            for (int i = 0; i < 4; ++i)
#pragma unroll
                for (int s = 0; s < 8; ++s)
                    sm.cand[tyl * 4 + i][tx * 8 + s] = lst[i][s];
        }
        __syncthreads();
        if (tid < 32) {
            int r = tid;
#pragma unroll
            for (int s = 0; s < KNB; ++s) {
                unsigned long long m = ~0ULL;
                int mi = 0;
                for (int q = 0; q < 128; ++q) {
                    unsigned long long v = sm.cand[r][q];
                    if (v < m) { m = v; mi = q; }
                }
                sm.cand[r][mi] = ~0ULL;
                g_idx[(rowBase + half * 32 + r) * KNB + s] = (int)(m & 8191ULL);
            }
        }
        __syncthreads();
    }
}

// ---------------------------------------------------------------------------
// Kernel 3: fused gather. out[bc, j] = in[bc, g_idx[j]].
// Index chunk staged in smem; one idx-chunk reused across 8 bc slices so the
// L2 read traffic stays ~1x of the output size. Coalesced float4 stores.
// ---------------------------------------------------------------------------
__global__ void gather_kernel(const float* __restrict__ in, float* __restrict__ out) {
    __shared__ int sidx[8192];
    const int jbase = blockIdx.x * 8192;
    for (int i = threadIdx.x; i < 8192; i += 256) sidx[i] = g_idx[jbase + i];
    __syncthreads();
    const int bc0 = blockIdx.y * 8;
#pragma unroll
    for (int e = 0; e < 8; ++e) {
        int bc = bc0 + e;
        const float* ip = in + bc * NF;
        float* op = out + (size_t)bc * (NF * KNB) + jbase;
        for (int t = threadIdx.x * 4; t < 8192; t += 1024) {
            float4 v;
            v.x = ip[sidx[t]];
            v.y = ip[sidx[t + 1]];
            v.z = ip[sidx[t + 2]];
            v.w = ip[sidx[t + 3]];
            *(float4*)&op[t] = v;
        }
    }
}

// ---------------------------------------------------------------------------
extern "C" void kernel_launch(void* const* d_in, const int* in_sizes, int n_in,
                              void* d_out, int out_size) {
    const float* d_inputs = (const float*)d_in[0];  // (64,4,8192,1) fp32
    const float* d_coords = (const float*)d_in[1];  // (64,1,8192)  fp32
    // Robustness: detect swapped metadata order via element counts.
    if (n_in >= 2 && in_sizes[0] == NF * ND && in_sizes[1] == 64 * 4 * NF) {
        const float* t = d_inputs; d_inputs = d_coords; d_coords = t;
    }

    sq_kernel<<<NF / 256, 256>>>(d_coords);
    topk_kernel<<<NF / RT, 256>>>(d_coords);
    gather_kernel<<<dim3(8, 32), 256>>>(d_inputs, (float*)d_out);
    (void)out_size; (void)n_in;
}

// round 11
// speedup vs baseline: 1.0012x; 1.0012x over previous
#include <cuda_runtime.h>

#define NF   8192   // features
#define ND   64     // coordinate dim
#define KNB  8      // neighbors
#define RT   64     // rows per CTA
#define CT   128    // cols per chunk

// Scratch: __device__ globals (no allocation allowed anywhere).
__device__ __align__(16) float g_sq[NF];
__device__ __align__(16) int   g_idx[NF * KNB];

// ---------------------------------------------------------------------------
// Kernel 1: per-feature squared norm. coordinates layout: [dim][feature].
// Matches reference's sum(square(x)) with separate mul+add rounding.
// ---------------------------------------------------------------------------
__global__ void sq_kernel(const float* __restrict__ crd) {
    int f = blockIdx.x * 256 + threadIdx.x;
    float s = 0.f;
#pragma unroll
    for (int d = 0; d < ND; ++d) {
        float c = crd[d * NF + f];
        s = __fadd_rn(s, __fmul_rn(c, c));
    }
    g_sq[f] = s;
}

// ---------------------------------------------------------------------------
// Kernel 2: fused distance-GEMM + per-row top-8 (value asc, index asc).
// Key = (float_bits(dist) << 13) | col  -> single u64 lexicographic compare.
// ---------------------------------------------------------------------------
__global__ __launch_bounds__(256) void topk_kernel(const float* __restrict__ crd) {
    __shared__ __align__(16) union {
        struct { float rowT[ND][RT]; float colT[ND][CT]; } t;  // 16KB + 32KB
        unsigned long long cand[32][129];                       // 33KB (padded vs bank conflicts)
    } sm;

    const int tid = threadIdx.x;
    const int tx  = tid & 15;          // 16 col-groups  (8 cols each)
    const int ty  = tid >> 4;          // 16 row-groups  (4 rows each)
    const int rowBase = blockIdx.x * RT;

    // Load row tile, [dim][row] layout (coordinates are already [dim][feature]).
    for (int i = tid; i < ND * RT / 4; i += 256) {
        int d = i >> 4, r4 = i & 15;
        *(float4*)&sm.t.rowT[d][r4 * 4] =
            *(const float4*)&crd[d * NF + rowBase + r4 * 4];
    }

    // Per-thread top-8 state for 4 rows: u64 keys + cached max + sqrt gate.
    unsigned long long lst[4][8];
    unsigned long long cmax[4];
    float gate[4];
    const unsigned long long INFKEY = ((unsigned long long)0x7F800000u) << 13;
#pragma unroll
    for (int i = 0; i < 4; ++i) {
#pragma unroll
        for (int s = 0; s < 8; ++s) lst[i][s] = INFKEY | (unsigned)s;  // distinct sentinels
        cmax[i] = INFKEY | 7u;
        gate[i] = __int_as_float(0x7F800000);  // +inf
    }

    float sqr[4];
#pragma unroll
    for (int i = 0; i < 4; ++i) sqr[i] = g_sq[rowBase + ty * 4 + i];

    for (int cb = 0; cb < NF; cb += CT) {
        __syncthreads();  // previous chunk fully consumed
        for (int i = tid; i < ND * CT / 4; i += 256) {
            int d = i >> 5, c4 = i & 31;
            *(float4*)&sm.t.colT[d][c4 * 4] =
                *(const float4*)&crd[d * NF + cb + c4 * 4];
        }
        __syncthreads();

        float sqc[8];
        {
            float4 s0 = *(const float4*)&g_sq[cb + tx * 8];
            float4 s1 = *(const float4*)&g_sq[cb + tx * 8 + 4];
            sqc[0]=s0.x; sqc[1]=s0.y; sqc[2]=s0.z; sqc[3]=s0.w;
            sqc[4]=s1.x; sqc[5]=s1.y; sqc[6]=s1.z; sqc[7]=s1.w;
        }

        float acc[4][8];
#pragma unroll
        for (int i = 0; i < 4; ++i)
#pragma unroll
            for (int j = 0; j < 8; ++j) acc[i][j] = 0.f;

        // Main GEMM micro-kernel: 3 x LDS.128 + 32 FFMA per k-step.
#pragma unroll 8
        for (int kk = 0; kk < ND; ++kk) {
            float4 a  = *(const float4*)&sm.t.rowT[kk][ty * 4];
            float4 b0 = *(const float4*)&sm.t.colT[kk][tx * 8];
            float4 b1 = *(const float4*)&sm.t.colT[kk][tx * 8 + 4];
            float av[4] = {a.x, a.y, a.z, a.w};
            float bv[8] = {b0.x, b0.y, b0.z, b0.w, b1.x, b1.y, b1.z, b1.w};
#pragma unroll
            for (int i = 0; i < 4; ++i)
#pragma unroll
                for (int j = 0; j < 8; ++j)
                    acc[i][j] = fmaf(av[i], bv[j], acc[i][j]);
        }

        // Selection update. Replicate reference elementwise ops exactly:
        // d = (-2*dot + sq_col) + sq_row; dist = sqrt(max(d,0)).
#pragma unroll
        for (int j = 0; j < 8; ++j) {
            int col = cb + tx * 8 + j;
#pragma unroll
            for (int i = 0; i < 4; ++i) {
                float t0  = __fadd_rn(__fmul_rn(-2.f, acc[i][j]), sqc[j]);
                float dsq = __fadd_rn(t0, sqr[i]);
                if (dsq < gate[i]) {   // cheap gate: skip sqrt for ~96% of candidates
                    float dist = __fsqrt_rn(fmaxf(dsq, 0.f));
                    unsigned long long key =
                        (((unsigned long long)__float_as_uint(dist)) << 13) |
                        (unsigned)col;
                    if (key < cmax[i]) {
#pragma unroll
                        for (int s = 0; s < 8; ++s)   // keys unique -> exactly one match
                            if (lst[i][s] == cmax[i]) lst[i][s] = key;
                        unsigned long long m = lst[i][0];
#pragma unroll
                        for (int s = 1; s < 8; ++s) m = (lst[i][s] > m) ? lst[i][s] : m;
                        cmax[i] = m;
                        float dm = __uint_as_float((unsigned)(cmax[i] >> 13));
                        // gate margin guarantees no legit (dist-tie, lower-idx) candidate is skipped
                        gate[i] = __fmul_rn(__fmul_rn(dm, dm), 1.00001f);
                    }
                }
            }
        }
    }

    // Merge 16 column-group lists per row -> final sorted top-8. Two halves
    // of 32 rows so the candidate buffer fits in the smem union.
    __syncthreads();
    for (int half = 0; half < 2; ++half) {
        if ((ty >> 3) == half) {
            int tyl = ty & 7;
#pragma unroll
            for (int i = 0; i < 4; ++i)
#pragma unroll
                for (int s = 0; s < 8; ++s)
                    sm.cand[tyl * 4 + i][tx * 8 + s] = lst[i][s];
        }
        __syncthreads();
        if (tid < 32) {
            int r = tid;
#pragma unroll
            for (int s = 0; s < KNB; ++s) {
                unsigned long long m = ~0ULL;
                int mi = 0;
                for (int q = 0; q < 128; ++q) {
                    unsigned long long v = sm.cand[r][q];
                    if (v < m) { m = v; mi = q; }
                }
                sm.cand[r][mi] = ~0ULL;
                g_idx[(rowBase + half * 32 + r) * KNB + s] = (int)(m & 8191ULL);
            }
        }
        __syncthreads();
    }
}

// ---------------------------------------------------------------------------
// Kernel 3: fused gather. out[bc, j] = in[bc, g_idx[j]].
// Index chunk staged in smem; one idx-chunk reused across 8 bc slices so the
// L2 read traffic stays ~1x of the output size. Coalesced float4 stores.
// ---------------------------------------------------------------------------
__global__ void gather_kernel(const float* __restrict__ in, float* __restrict__ out) {
    __shared__ int sidx[8192];
    const int jbase = blockIdx.x * 8192;
    for (int i = threadIdx.x; i < 8192; i += 256) sidx[i] = g_idx[jbase + i];
    __syncthreads();
    const int bc0 = blockIdx.y * 8;
#pragma unroll
    for (int e = 0; e < 8; ++e) {
        int bc = bc0 + e;
        const float* ip = in + bc * NF;
        float* op = out + (size_t)bc * (NF * KNB) + jbase;
        for (int t = threadIdx.x * 4; t < 8192; t += 1024) {
            float4 v;
            v.x = ip[sidx[t]];
            v.y = ip[sidx[t + 1]];
            v.z = ip[sidx[t + 2]];
            v.w = ip[sidx[t + 3]];
            *(float4*)&op[t] = v;
        }
    }
}

// ---------------------------------------------------------------------------
extern "C" void kernel_launch(void* const* d_in, const int* in_sizes, int n_in,
                              void* d_out, int out_size) {
    const float* d_inputs = (const float*)d_in[0];  // (64,4,8192,1) fp32
    const float* d_coords = (const float*)d_in[1];  // (64,1,8192)  fp32
    // Robustness: detect swapped metadata order via element counts.
    if (n_in >= 2 && in_sizes[0] == NF * ND && in_sizes[1] == 64 * 4 * NF) {
        const float* t = d_inputs; d_inputs = d_coords; d_coords = t;
    }

    sq_kernel<<<NF / 256, 256>>>(d_coords);
    topk_kernel<<<NF / RT, 256>>>(d_coords);
    gather_kernel<<<dim3(8, 32), 256>>>(d_inputs, (float*)d_out);
    (void)out_size; (void)n_in;
}

// round 12
// speedup vs baseline: 1.2488x; 1.2473x over previous
#include <cuda_runtime.h>

#define NF   8192   // features
#define ND   64     // coordinate dim
#define KNB  8      // neighbors
#define RT   64     // rows per CTA
#define CT   128    // cols per chunk
#define NC   (NF / CT)
#define THREADS 512

// Scratch: __device__ globals (no allocation allowed anywhere).
__device__ __align__(16) float g_sq[NF];
__device__ __align__(16) int   g_idx[NF * KNB];

// ---------------------------------------------------------------------------
// Kernel 1: per-feature squared norm. coordinates layout: [dim][feature].
// Matches reference's sum(square(x)) with separate mul+add rounding.
// ---------------------------------------------------------------------------
__global__ void sq_kernel(const float* __restrict__ crd) {
    int f = blockIdx.x * 256 + threadIdx.x;
    float s = 0.f;
#pragma unroll
    for (int d = 0; d < ND; ++d) {
        float c = crd[d * NF + f];
        s = __fadd_rn(s, __fmul_rn(c, c));
    }
    g_sq[f] = s;
}

// 16-byte async copy global -> shared (bypass L1; data is L2-shared by all CTAs)
__device__ __forceinline__ void cp16(void* dst, const void* src) {
    unsigned d = (unsigned)__cvta_generic_to_shared(dst);
    asm volatile("cp.async.cg.shared.global [%0], [%1], 16;\n" :: "r"(d), "l"(src));
}

// ---------------------------------------------------------------------------
// Kernel 2: fused distance-GEMM + per-row top-8 (value asc, index asc).
// 512 threads: tx = lane (32 col-groups x 4 cols), ty = warp (16 row-groups
// x 4 rows). Per k-step per warp: 1 broadcast LDS.128 (a) + 1 conflict-free
// LDS.128 (b) + 16 FFMA. Column tiles double-buffered via cp.async.
// Key = (float_bits(dist) << 13) | col  -> single u64 lexicographic compare.
// ---------------------------------------------------------------------------
extern __shared__ float smem[];
// layout: rowT[ND][RT] (16KB) | colT0[ND][CT] (32KB) | colT1[ND][CT] (32KB)

__global__ __launch_bounds__(THREADS, 1) void topk_kernel(const float* __restrict__ crd) {
    float (*rowT)[RT]  = (float (*)[RT])smem;
    float (*colT0)[CT] = (float (*)[CT])(smem + ND * RT);
    float (*colT1)[CT] = (float (*)[CT])(smem + ND * RT + ND * CT);

    const int tid  = threadIdx.x;
    const int tx   = tid & 31;   // lane: 32 col-groups of 4 cols
    const int ty   = tid >> 5;   // warp: 16 row-groups of 4 rows
    const int rowBase = blockIdx.x * RT;

    // Load row tile [dim][row] (coordinates are already [dim][feature]).
    for (int i = tid; i < ND * RT / 4; i += THREADS) {
        int d = i >> 4, r4 = i & 15;
        *(float4*)&rowT[d][r4 * 4] = *(const float4*)&crd[d * NF + rowBase + r4 * 4];
    }

    // Prefetch chunk 0 into colT0.
#pragma unroll
    for (int q = 0; q < 4; ++q) {
        int idx = tid + THREADS * q;        // 0..2047 float4
        int d = idx >> 5, c4 = idx & 31;
        cp16(&colT0[d][c4 * 4], &crd[d * NF + c4 * 4]);
    }
    asm volatile("cp.async.commit_group;\n");

    // Per-thread top-8 state for 4 rows: u64 keys + cached max + sqrt gate.
    unsigned long long lst[4][8];
    unsigned long long cmax[4];
    float gate[4];
    const unsigned long long INFKEY = ((unsigned long long)0x7F800000u) << 13;
#pragma unroll
    for (int i = 0; i < 4; ++i) {
#pragma unroll
        for (int s = 0; s < 8; ++s) lst[i][s] = INFKEY | (unsigned)s;  // distinct sentinels
        cmax[i] = INFKEY | 7u;
        gate[i] = __int_as_float(0x7F800000);  // +inf
    }

    float sqr[4];
#pragma unroll
    for (int i = 0; i < 4; ++i) sqr[i] = g_sq[rowBase + ty * 4 + i];

    for (int c = 0; c < NC; ++c) {
        float (*cur)[CT] = (c & 1) ? colT1 : colT0;
        // Prefetch next chunk into the other buffer (safe: trailing sync of
        // iteration c-1 guarantees everyone finished reading it).
        if (c + 1 < NC) {
            float (*nxt)[CT] = (c & 1) ? colT0 : colT1;
            const float* src = crd + (c + 1) * CT;
#pragma unroll
            for (int q = 0; q < 4; ++q) {
                int idx = tid + THREADS * q;
                int d = idx >> 5, c4 = idx & 31;
                cp16(&nxt[d][c4 * 4], src + d * NF + c4 * 4);
            }
            asm volatile("cp.async.commit_group;\n");
            asm volatile("cp.async.wait_group 1;\n");  // chunk c complete
        } else {
            asm volatile("cp.async.wait_group 0;\n");
        }
        __syncthreads();

        float sqc[4];
        {
            float4 s0 = *(const float4*)&g_sq[c * CT + tx * 4];
            sqc[0] = s0.x; sqc[1] = s0.y; sqc[2] = s0.z; sqc[3] = s0.w;
        }

        float acc[4][4];
#pragma unroll
        for (int i = 0; i < 4; ++i)
#pragma unroll
            for (int j = 0; j < 4; ++j) acc[i][j] = 0.f;

        // GEMM micro-kernel: 2 x LDS.128 + 16 FFMA per k-step.
#pragma unroll 8
        for (int kk = 0; kk < ND; ++kk) {
            float4 a = *(const float4*)&rowT[kk][ty * 4];   // warp broadcast
            float4 b = *(const float4*)&cur[kk][tx * 4];    // 512B conflict-free
            float av[4] = {a.x, a.y, a.z, a.w};
            float bv[4] = {b.x, b.y, b.z, b.w};
#pragma unroll
            for (int i = 0; i < 4; ++i)
#pragma unroll
                for (int j = 0; j < 4; ++j)
                    acc[i][j] = fmaf(av[i], bv[j], acc[i][j]);
        }

        // Buffer released: selection below is register-only, so sync here to
        // unblock the next iteration's prefetch as early as possible.
        __syncthreads();

        // Selection update. Replicate reference elementwise ops exactly:
        // d = (-2*dot + sq_col) + sq_row; dist = sqrt(max(d,0)).
#pragma unroll
        for (int j = 0; j < 4; ++j) {
            int col = c * CT + tx * 4 + j;
#pragma unroll
            for (int i = 0; i < 4; ++i) {
                float t0  = __fadd_rn(__fmul_rn(-2.f, acc[i][j]), sqc[j]);
                float dsq = __fadd_rn(t0, sqr[i]);
                if (dsq < gate[i]) {   // cheap gate: skip sqrt for ~96% of candidates
                    float dist = __fsqrt_rn(fmaxf(dsq, 0.f));
                    unsigned long long key =
                        (((unsigned long long)__float_as_uint(dist)) << 13) |
                        (unsigned)col;
                    if (key < cmax[i]) {
#pragma unroll
                        for (int s = 0; s < 8; ++s)   // keys unique -> exactly one match
                            if (lst[i][s] == cmax[i]) lst[i][s] = key;
                        unsigned long long m = lst[i][0];
#pragma unroll
                        for (int s = 1; s < 8; ++s) m = (lst[i][s] > m) ? lst[i][s] : m;
                        cmax[i] = m;
                        float dm = __uint_as_float((unsigned)(cmax[i] >> 13));
                        // gate margin guarantees no legit (dist-tie, lower-idx)
                        // candidate is ever skipped
                        gate[i] = __fmul_rn(__fmul_rn(dm, dm), 1.00001f);
                    }
                }
            }
        }
    }

    // Warp-local merge: all 32 partial lists for a row live in this warp
    // (tx == lane). 8 extraction rounds of u64 shuffle-min. No smem needed.
#pragma unroll
    for (int i = 0; i < 4; ++i) {
        const int row = rowBase + ty * 4 + i;
        for (int s = 0; s < KNB; ++s) {
            unsigned long long m = lst[i][0];
#pragma unroll
            for (int t = 1; t < 8; ++t) m = (lst[i][t] < m) ? lst[i][t] : m;
#pragma unroll
            for (int off = 16; off; off >>= 1) {
                unsigned long long o = __shfl_xor_sync(0xffffffffu, m, off);
                if (o < m) m = o;
            }
            // Remove the winner (keys are globally unique -> exactly one slot).
#pragma unroll
            for (int t = 0; t < 8; ++t)
                if (lst[i][t] == m) lst[i][t] = ~0ULL;
            if (tx == 0) g_idx[row * KNB + s] = (int)(m & 8191ULL);
        }
    }
}

// ---------------------------------------------------------------------------
// Kernel 3: fused gather. out[bc, j] = in[bc, g_idx[j]].
// Index chunk staged in smem; one idx-chunk reused across 8 bc slices so the
// L2 read traffic stays ~1x of the output size. Coalesced float4 stores.
// ---------------------------------------------------------------------------
__global__ void gather_kernel(const float* __restrict__ in, float* __restrict__ out) {
    __shared__ int sidx[8192];
    const int jbase = blockIdx.x * 8192;
    for (int i = threadIdx.x; i < 8192; i += 256) sidx[i] = g_idx[jbase + i];
    __syncthreads();
    const int bc0 = blockIdx.y * 8;
#pragma unroll
    for (int e = 0; e < 8; ++e) {
        int bc = bc0 + e;
        const float* ip = in + bc * NF;
        float* op = out + (size_t)bc * (NF * KNB) + jbase;
        for (int t = threadIdx.x * 4; t < 8192; t += 1024) {
            float4 v;
            v.x = ip[sidx[t]];
            v.y = ip[sidx[t + 1]];
            v.z = ip[sidx[t + 2]];
            v.w = ip[sidx[t + 3]];
            *(float4*)&op[t] = v;
        }
    }
}

// ---------------------------------------------------------------------------
extern "C" void kernel_launch(void* const* d_in, const int* in_sizes, int n_in,
                              void* d_out, int out_size) {
    const float* d_inputs = (const float*)d_in[0];  // (64,4,8192,1) fp32
    const float* d_coords = (const float*)d_in[1];  // (64,1,8192)  fp32
    // Robustness: detect swapped metadata order via element counts.
    if (n_in >= 2 && in_sizes[0] == NF * ND && in_sizes[1] == 64 * 4 * NF) {
        const float* t = d_inputs; d_inputs = d_coords; d_coords = t;
    }

    const int smem_bytes = (ND * RT + 2 * ND * CT) * (int)sizeof(float);  // 81920
    cudaFuncSetAttribute(topk_kernel, cudaFuncAttributeMaxDynamicSharedMemorySize,
                         smem_bytes);

    sq_kernel<<<NF / 256, 256>>>(d_coords);
    topk_kernel<<<NF / RT, THREADS, smem_bytes>>>(d_coords);
    gather_kernel<<<dim3(8, 32), 256>>>(d_inputs, (float*)d_out);
    (void)out_size; (void)n_in;
}